// round 15
// baseline (speedup 1.0000x reference)
#include <cuda_runtime.h>
#include <cuda_bf16.h>

// PSAvgPooling: B=8, H=W=64, C=1152 (= 9 bins * 128), N=512 boxes/image,
// 3x3 bins x 3x3 crop samples, bilinear gather, weighted bin-average.
//
// R14: refined locality model. Bytes are shared between boxes only when the
// SAME-numbered bin rectangles overlap => requires similar SIZE and position.
// R12's position-only sort grouped boxes that share nothing.
//   1) sort key = (image | size-class y,x | 4x4 position), warp-shfl scan sort
//   2) 4 sorted boxes per 512-thread block, bin-lockstep sample order:
//      shared lines are touched within a tight temporal window -> L1 hits /
//      miss-queue coalescing cut L2->SM bytes (the saturated resource:
//      490MB / 41.3us ~= LTS cap).

namespace {

constexpr int Hh    = 64;
constexpr int Ww    = 64;
constexpr int Cc    = 1152;   // total channels
constexpr int Csz   = 128;    // channels per bin (Cc / 9)
constexpr int NSAMP = 81;     // 9 bins * 9 crop samples
constexpr int NWARP = 4;      // warps per box
constexpr int GBOX  = 4;      // boxes per block
constexpr int MAXBOX = 8192;

__device__ int g_order[MAXBOX];

__device__ __forceinline__ int box_key(const float* bx, int i, int nPerImage) {
    const float sy = bx[2] - bx[0];
    const float sx = bx[3] - bx[1];
    const float cy = (bx[0] + bx[2]) * 0.5f;
    const float cx = (bx[1] + bx[3]) * 0.5f;
    const int img = i / nPerImage;                      // 0..7
    const int ksy = sy > 0.225f ? 1 : 0;                // size class y
    const int ksx = sx > 0.225f ? 1 : 0;                // size class x
    const int ky  = min(3, max(0, (int)(cy * 4.0f)));   // 4x4 center bucket
    const int kx  = min(3, max(0, (int)(cx * 4.0f)));
    return ((img & 7) << 6) | (ksy << 5) | (ksx << 4) | (ky << 2) | kx;  // 512 buckets
}

// ---- Sort kernel: single block, 512 buckets, warp-shfl scan (2 barriers) ----
__global__ __launch_bounds__(512) void sort_boxes_kernel(
    const float* __restrict__ boxes, int n, int nPerImage)
{
    __shared__ int s_cnt[512];
    __shared__ int s_wsum[16];
    __shared__ int s_ofs[512];
    const int tid  = threadIdx.x;
    const int lane = tid & 31;
    const int wid  = tid >> 5;

    s_cnt[tid] = 0;
    __syncthreads();

    // histogram
    for (int i = tid; i < n && i < MAXBOX; i += 512)
        atomicAdd(&s_cnt[box_key(boxes + (size_t)i * 4, i, nPerImage)], 1);
    __syncthreads();

    // exclusive scan of 512 counts: warp inclusive scans + warp-sum scan
    const int v = s_cnt[tid];
    int incl = v;
    #pragma unroll
    for (int d = 1; d < 32; d <<= 1) {
        const int t = __shfl_up_sync(0xffffffffu, incl, d);
        if (lane >= d) incl += t;
    }
    if (lane == 31) s_wsum[wid] = incl;
    __syncthreads();
    if (wid == 0) {
        int wv = (lane < 16) ? s_wsum[lane] : 0;
        int wincl = wv;
        #pragma unroll
        for (int d = 1; d < 16; d <<= 1) {
            const int t = __shfl_up_sync(0xffffffffu, wincl, d);
            if (lane >= d) wincl += t;
        }
        if (lane < 16) s_wsum[lane] = wincl;   // inclusive warp sums
    }
    __syncthreads();
    const int base = (wid > 0) ? s_wsum[wid - 1] : 0;
    s_ofs[tid] = base + incl - v;              // exclusive prefix
    __syncthreads();

    // scatter sorted order
    for (int i = tid; i < n && i < MAXBOX; i += 512) {
        const int key = box_key(boxes + (size_t)i * 4, i, nPerImage);
        const int pos = atomicAdd(&s_ofs[key], 1);
        g_order[pos] = i;
    }
}

// ---- Main kernel: 4 sorted boxes per block, 4 warps per box (R2d loop) ----
__global__ __launch_bounds__(GBOX * NWARP * 32, 2) void ps_pool_kernel(
    const float* __restrict__ img,    // [B, H, W, C]
    const float* __restrict__ boxes,  // [B*N, 4]
    const float* __restrict__ wts,    // [9]
    float* __restrict__ out,          // [B*N, 128]
    int nPerImage, int totalBoxes)
{
    __shared__ int4   s_off[GBOX][NSAMP];
    __shared__ float4 s_w[GBOX][NSAMP];
    __shared__ float4 s_red[GBOX][NWARP][32];

    const int tid  = threadIdx.x;
    const int q    = tid >> 7;          // which box of the group (0..3)
    const int ht   = tid & 127;         // thread within box slice
    const int lane = tid & 31;
    const int warp = ht >> 5;           // warp within box (0..3)

    const int oidx   = min(blockIdx.x * GBOX + q, totalBoxes - 1);
    const int box_id = g_order[oidx];
    const int b      = box_id / nPerImage;
    const float* __restrict__ image = img + (size_t)b * (Hh * Ww * Cc);
    const float* bx = boxes + (size_t)box_id * 4;

    // ---- per-box sample setup (81 threads of each box slice) ----
    if (ht < NSAMP) {
        const float y1 = bx[0], x1 = bx[1], y2 = bx[2], x2 = bx[3];
        const float step_y = (y2 - y1) * (1.0f / 3.0f);
        const float step_x = (x2 - x1) * (1.0f / 3.0f);

        const int s   = ht;
        const int by  = s / 27;
        const int bxn = (s / 9) % 3;
        const int py  = (s / 3) % 3;
        const int px  = s % 3;

        const float yy = (y1 + ((float)by + (float)py * 0.5f) * step_y) * (float)(Hh - 1);
        const float xx = (x1 + ((float)bxn + (float)px * 0.5f) * step_x) * (float)(Ww - 1);

        const float y0f = floorf(yy);
        const float x0f = floorf(xx);
        const float wy = yy - y0f;
        const float wx = xx - x0f;
        const int y0 = (int)y0f;
        const int x0 = (int)x0f;

        const int y0c = min(max(y0,     0), Hh - 1);
        const int y1c = min(max(y0 + 1, 0), Hh - 1);
        const int x0c = min(max(x0,     0), Ww - 1);
        const int x1c = min(max(x0 + 1, 0), Ww - 1);

        const bool inside = (yy >= 0.0f) && (yy <= (float)(Hh - 1)) &&
                            (xx >= 0.0f) && (xx <= (float)(Ww - 1));
        const int bin = by * 3 + bxn;
        const float wb = inside ? wts[bin] : 0.0f;
        const int cb = bin * Csz;

        s_off[q][s] = make_int4(((y0c * Ww + x0c) * Cc + cb) * 4,
                                ((y0c * Ww + x1c) * Cc + cb) * 4,
                                ((y1c * Ww + x0c) * Cc + cb) * 4,
                                ((y1c * Ww + x1c) * Cc + cb) * 4);
        s_w[q][s] = make_float4(wb * (1.0f - wy) * (1.0f - wx),
                                wb * (1.0f - wy) * wx,
                                wb * wy * (1.0f - wx),
                                wb * wy * wx);
    }
    __syncthreads();

    // ---- gather: 4 warps per box, samples split across warps (bin-lockstep:
    //      all boxes walk the same s-order, so shared lines are co-touched) ----
    const char* __restrict__ base = (const char*)image + lane * 16;
    const int s_begin = (warp * NSAMP) / NWARP;
    const int s_end   = ((warp + 1) * NSAMP) / NWARP;

    float4 acc = make_float4(0.f, 0.f, 0.f, 0.f);

    #pragma unroll 4
    for (int s = s_begin; s < s_end; s++) {
        const int4   off = s_off[q][s];
        const float4 w   = s_w[q][s];
        const float4 v0 = __ldg((const float4*)(base + off.x));
        const float4 v1 = __ldg((const float4*)(base + off.y));
        const float4 v2 = __ldg((const float4*)(base + off.z));
        const float4 v3 = __ldg((const float4*)(base + off.w));
        acc.x += w.x * v0.x + w.y * v1.x + w.z * v2.x + w.w * v3.x;
        acc.y += w.x * v0.y + w.y * v1.y + w.z * v2.y + w.w * v3.y;
        acc.z += w.x * v0.z + w.y * v1.z + w.z * v2.z + w.w * v3.z;
        acc.w += w.x * v0.w + w.y * v1.w + w.z * v2.w + w.w * v3.w;
    }

    s_red[q][warp][lane] = acc;
    __syncthreads();

    // ---- warp 0 of each box slice reduces + writes its box ----
    if (warp == 0) {
        float4 a0 = s_red[q][0][lane];
        float4 a1 = s_red[q][1][lane];
        float4 a2 = s_red[q][2][lane];
        float4 a3 = s_red[q][3][lane];
        const float inv = 1.0f / 81.0f;
        float4 o;
        o.x = (a0.x + a1.x + a2.x + a3.x) * inv;
        o.y = (a0.y + a1.y + a2.y + a3.y) * inv;
        o.z = (a0.z + a1.z + a2.z + a3.z) * inv;
        o.w = (a0.w + a1.w + a2.w + a3.w) * inv;
        reinterpret_cast<float4*>(out)[(size_t)box_id * (Csz / 4) + lane] = o;
    }
}

} // namespace

extern "C" void kernel_launch(void* const* d_in, const int* in_sizes, int n_in,
                              void* d_out, int out_size) {
    const float* img   = (const float*)d_in[0];  // [B,64,64,1152] fp32
    const float* boxes = (const float*)d_in[1];  // [B,N,4] fp32
    const float* wts   = (const float*)d_in[2];  // [9] fp32
    float* out = (float*)d_out;                  // [B*N, 128] fp32

    const int B          = in_sizes[0] / (Hh * Ww * Cc);
    const int totalBoxes = in_sizes[1] / 4;
    const int nPerImage  = totalBoxes / B;

    sort_boxes_kernel<<<1, 512>>>(boxes, totalBoxes, nPerImage);

    const int numGroups = (totalBoxes + GBOX - 1) / GBOX;
    ps_pool_kernel<<<numGroups, GBOX * NWARP * 32>>>(
        img, boxes, wts, out, nPerImage, totalBoxes);
}